// round 6
// baseline (speedup 1.0000x reference)
#include <cuda_runtime.h>

#define BB 16
#define HH 512
#define WW 512
#define PL (HH*WW)            // 262144 elems per channel plane
#define NPIX (BB*PL)          // 4194304 pixels per input set
#define P1_BLOCKS (32*256)    // pass1 blocks
#define P2_BLOCKS 512
#define CAP (1<<22)           // candidate capacity (4M)
#define CAND_T 0.0165f        // conservative: 0.001*mean <= 0.016 since ssd < 16

// Static scratch
__device__ float    g_part1[P1_BLOCKS];
__device__ float    g_part2[P2_BLOCKS];
__device__ unsigned g_cand_idx[CAP];   // bit31 = which (0=src,1=tgt), low = pixel idx
__device__ float    g_cand_val[CAP];
__device__ unsigned g_cand_n;
__device__ unsigned g_done1, g_done2;
__device__ float    g_sumS, g_sumT;    // sum of ssd per input set

__device__ __forceinline__ int clampi(int v, int lo, int hi) {
    return min(max(v, lo), hi);
}

// diff^2 at clamped center (cy,cx) — SAME op order everywhere (bit-exact).
__device__ __forceinline__ float diff2_at(const float* __restrict__ I0,
                                          const float* __restrict__ I1,
                                          const float* __restrict__ I2,
                                          int cy, int cx) {
    int ym = max(cy - 2, 0), yp = min(cy + 2, HH - 1);
    int xm = max(cx - 2, 0), xp = min(cx + 2, WW - 1);
    float d = I0[cy * WW + xm] + I0[yp * WW + xp]
            + I1[yp * WW + xm] + I2[yp * WW + xm]
            - I0[ym * WW + cx] - I1[cy * WW + xm]
            - I2[ym * WW + cx] - I2[yp * WW + xp];
    return d * d;
}

// ssd at pixel (y,x) of an image — bit-exact replica of pass1's 3-stage order.
__device__ float ssd_at(const float* __restrict__ img, int y, int x) {
    const float* I0 = img;
    const float* I1 = img + PL;
    const float* I2 = img + 2 * PL;
    float acc = 0.f;
    #pragma unroll
    for (int dy = -2; dy <= 2; dy++) {
        int yy = clampi(y + dy, 0, HH - 1);
        float hs = 0.f;
        #pragma unroll
        for (int dx = -2; dx <= 2; dx++) {
            int xx = clampi(x + dx, 0, WW - 1);
            hs += diff2_at(I0, I1, I2, yy, xx);
        }
        acc += hs;
    }
    return acc * (1.0f / 25.0f);
}

// ---------------------------------------------------------------------------
// Pass 1: ssd per pixel (never stored) -> per-block partial sums + candidates.
// Last block reduces partials -> g_sumS/g_sumT. grid (16,16,32), block (32,8).
// ---------------------------------------------------------------------------
__global__ __launch_bounds__(256) void k_pass1(const float* __restrict__ src,
                                               const float* __restrict__ tgt) {
    __shared__ float s_in[3][40][48];   // staged planes (interior tiles)
    __shared__ float s_d2[36][40];      // diff^2 with +-2 halo
    __shared__ float s_h[36][33];       // horizontal 5-sums
    __shared__ float s_red[8];
    __shared__ int   s_last;

    const int tz    = blockIdx.z;
    const int which = tz >> 4;
    const int b     = tz & 15;
    const float* img = (which ? tgt : src) + (size_t)b * 4 * PL;
    const float* __restrict__ I0 = img;
    const float* __restrict__ I1 = img + PL;
    const float* __restrict__ I2 = img + 2 * PL;

    const int bx = blockIdx.x, by = blockIdx.y;
    const int tx0 = bx * 32;
    const int ty0 = by * 32;
    const int t   = threadIdx.y * 32 + threadIdx.x;
    const bool interior = (bx >= 1) && (bx <= 14) && (by >= 1) && (by <= 14);

    if (interior) {
        // Stage planes: rows [ty0-4, ty0+36), cols [tx0-8, tx0+40) (48-wide, f4-aligned)
        for (int i = t; i < 3 * 40 * 12; i += 256) {
            int p = i / 480; int r2 = i - p * 480;
            int r = r2 / 12; int cq = r2 - r * 12;
            const float* Ip = (p == 0) ? I0 : ((p == 1) ? I1 : I2);
            float4 v = *(const float4*)(Ip + (ty0 - 4 + r) * WW + (tx0 - 8) + cq * 4);
            *(float4*)&s_in[p][r][cq * 4] = v;
        }
        __syncthreads();
        // diff^2 over 36x36 halo, from SMEM (same op order as diff2_at)
        for (int i = t; i < 36 * 36; i += 256) {
            int ty = i / 36, tx = i - ty * 36;
            float d = s_in[0][ty + 2][tx + 4] + s_in[0][ty + 4][tx + 8]
                    + s_in[1][ty + 4][tx + 4] + s_in[2][ty + 4][tx + 4]
                    - s_in[0][ty    ][tx + 6] - s_in[1][ty + 2][tx + 4]
                    - s_in[2][ty    ][tx + 6] - s_in[2][ty + 4][tx + 8];
            s_d2[ty][tx] = d * d;
        }
    } else {
        for (int i = t; i < 36 * 36; i += 256) {
            int ty = i / 36, tx = i - ty * 36;
            int cy = clampi(ty0 - 2 + ty, 0, HH - 1);
            int cx = clampi(tx0 - 2 + tx, 0, WW - 1);
            s_d2[ty][tx] = diff2_at(I0, I1, I2, cy, cx);
        }
    }
    __syncthreads();

    // Horizontal 5-sum
    if (interior) {
        for (int i = t; i < 36 * 32; i += 256) {
            int r = i >> 5, c = i & 31;
            s_h[r][c] = s_d2[r][c] + s_d2[r][c + 1] + s_d2[r][c + 2]
                      + s_d2[r][c + 3] + s_d2[r][c + 4];
        }
    } else {
        for (int i = t; i < 36 * 32; i += 256) {
            int r = i >> 5, c = i & 31;
            int gx = tx0 + c;
            float s = 0.f;
            #pragma unroll
            for (int dx = -2; dx <= 2; dx++) {
                int sx = clampi(gx + dx, 0, WW - 1) - tx0 + 2;
                s += s_d2[r][sx];
            }
            s_h[r][c] = s;
        }
    }
    __syncthreads();

    // Vertical 5-sum, accumulate, record candidates
    float lsum = 0.f;
    const int c = threadIdx.x;
    #pragma unroll
    for (int k = 0; k < 4; k++) {
        int y  = threadIdx.y + k * 8;
        int gy = ty0 + y;
        float s;
        if (interior) {
            s = s_h[y][c] + s_h[y + 1][c] + s_h[y + 2][c]
              + s_h[y + 3][c] + s_h[y + 4][c];
        } else {
            s = 0.f;
            #pragma unroll
            for (int dy = -2; dy <= 2; dy++) {
                int sy = clampi(gy + dy, 0, HH - 1) - ty0 + 2;
                s += s_h[sy][c];
            }
        }
        s *= (1.0f / 25.0f);
        lsum += s;
        if (s < CAND_T) {
            unsigned slot = atomicAdd(&g_cand_n, 1u);
            if (slot < CAP) {
                g_cand_idx[slot] = ((unsigned)which << 31)
                                 | (unsigned)(b * PL + gy * WW + tx0 + c);
                g_cand_val[slot] = s;
            }
        }
    }

    // block reduction -> per-block partial
    #pragma unroll
    for (int o = 16; o; o >>= 1) lsum += __shfl_down_sync(0xffffffffu, lsum, o);
    if (threadIdx.x == 0) s_red[threadIdx.y] = lsum;
    __syncthreads();
    if (t < 8) {
        float v = s_red[t];
        #pragma unroll
        for (int o = 4; o; o >>= 1) v += __shfl_down_sync(0xffu, v, o);
        if (t == 0) g_part1[tz * 256 + by * 16 + bx] = v;
    }

    // last-block-done: reduce all partials -> g_sumS, g_sumT
    if (t == 0) {
        __threadfence();
        unsigned v = atomicAdd(&g_done1, 1u);
        s_last = (v == P1_BLOCKS - 1);
    }
    __syncthreads();
    if (s_last) {
        // first 4096 partials = source, second 4096 = target
        float accS = 0.f, accT = 0.f;
        const float4* p4 = (const float4*)g_part1;
        #pragma unroll
        for (int j = 0; j < 4; j++) {
            float4 a = p4[t * 4 + j];
            accS += a.x + a.y + a.z + a.w;
            float4 bq = p4[1024 + t * 4 + j];
            accT += bq.x + bq.y + bq.z + bq.w;
        }
        #pragma unroll
        for (int o = 16; o; o >>= 1) {
            accS += __shfl_down_sync(0xffffffffu, accS, o);
            accT += __shfl_down_sync(0xffffffffu, accT, o);
        }
        __shared__ float sS[8], sT[8];
        if ((t & 31) == 0) { sS[t >> 5] = accS; sT[t >> 5] = accT; }
        __syncthreads();
        if (t == 0) {
            float fS = 0.f, fT = 0.f;
            #pragma unroll
            for (int j = 0; j < 8; j++) { fS += sS[j]; fT += sT[j]; }
            g_sumS = fS; g_sumT = fT;
            g_done1 = 0;   // reset for next graph replay
        }
    }
}

// ---------------------------------------------------------------------------
// Pass 2: loss from candidates only (unclipped pairs contribute exactly 0).
// Fallback full recompute if upper clip possible or candidate overflow.
// Last block reduces partials, writes out, resets state.
// ---------------------------------------------------------------------------
__global__ __launch_bounds__(256) void k_pass2(const float* __restrict__ src,
                                               const float* __restrict__ tgt,
                                               float* __restrict__ out) {
    const float sumS = g_sumS, sumT = g_sumT;
    const float meanS = sumS * (1.0f / (float)NPIX);
    const float meanT = sumT * (1.0f / (float)NPIX);
    const unsigned cn = g_cand_n;
    const bool full = (meanS < CAND_T) || (meanT < CAND_T) || (cn > CAP);
    const unsigned n = cn > CAP ? CAP : cn;

    const float mv_s = (float)((double)sumS / (4.0 * (double)NPIX));
    const float mv_t = (float)((double)sumT / (4.0 * (double)NPIX));
    const float lo_s = mv_s * 0.001f, hi_s = mv_s * 1000.0f;
    const float lo_t = mv_t * 0.001f, hi_t = mv_t * 1000.0f;

    const int tid = blockIdx.x * 256 + threadIdx.x;
    const int stride = gridDim.x * 256;
    float acc = 0.f;

    if (!full) {
        for (unsigned e = tid; e < n; e += stride) {
            unsigned rec = g_cand_idx[e];
            float val = g_cand_val[e];
            int w = rec >> 31;
            unsigned idx = rec & 0x7fffffffu;
            int b = idx / PL; int rem = idx - b * PL;
            int y = rem / WW; int x = rem - y * WW;
            const float* oimg = (w ? src : tgt) + (size_t)b * 4 * PL;
            float other = ssd_at(oimg, y, x);
            float a, bt;
            if (w == 0) { a = val; bt = other; }
            else {
                a = other; bt = val;
                if (a * 0.25f < lo_s) continue;   // already counted by source entry
            }
            float va = fminf(fmaxf(a  * 0.25f, lo_s), hi_s);
            float vb = fminf(fmaxf(bt * 0.25f, lo_t), hi_t);
            float d = __expf(-a / va) - __expf(-bt / vb);
            acc += d * d;
        }
    } else {
        // never-taken safety path: full recompute of both ssd fields
        for (long i = tid; i < (long)NPIX; i += stride) {
            int b = (int)(i / PL); int rem = (int)(i - (long)b * PL);
            int y = rem / WW; int x = rem - y * WW;
            float a  = ssd_at(src + (size_t)b * 4 * PL, y, x);
            float bt = ssd_at(tgt + (size_t)b * 4 * PL, y, x);
            float va = fminf(fmaxf(a  * 0.25f, lo_s), hi_s);
            float vb = fminf(fmaxf(bt * 0.25f, lo_t), hi_t);
            float d = __expf(-a / va) - __expf(-bt / vb);
            acc += d * d;
        }
    }

    __shared__ float s_red[8];
    __shared__ int   s_last;
    #pragma unroll
    for (int o = 16; o; o >>= 1) acc += __shfl_down_sync(0xffffffffu, acc, o);
    if ((threadIdx.x & 31) == 0) s_red[threadIdx.x >> 5] = acc;
    __syncthreads();
    if (threadIdx.x < 8) {
        float v = s_red[threadIdx.x];
        #pragma unroll
        for (int o = 4; o; o >>= 1) v += __shfl_down_sync(0xffu, v, o);
        if (threadIdx.x == 0) g_part2[blockIdx.x] = v;
    }

    if (threadIdx.x == 0) {
        __threadfence();
        unsigned v = atomicAdd(&g_done2, 1u);
        s_last = (v == P2_BLOCKS - 1);
    }
    __syncthreads();
    if (s_last) {
        float a2 = (threadIdx.x < P2_BLOCKS) ? g_part2[threadIdx.x] : 0.f;
        float a3 = (threadIdx.x + 256 < P2_BLOCKS) ? g_part2[threadIdx.x + 256] : 0.f;
        float v = a2 + a3;
        #pragma unroll
        for (int o = 16; o; o >>= 1) v += __shfl_down_sync(0xffffffffu, v, o);
        __shared__ float s_f[8];
        if ((threadIdx.x & 31) == 0) s_f[threadIdx.x >> 5] = v;
        __syncthreads();
        if (threadIdx.x == 0) {
            float tot = 0.f;
            #pragma unroll
            for (int j = 0; j < 8; j++) tot += s_f[j];
            out[0] = (float)((double)tot / (3.0 * (double)NPIX));
            g_done2 = 0;
            g_cand_n = 0;   // reset for next graph replay
        }
    }
}

extern "C" void kernel_launch(void* const* d_in, const int* in_sizes, int n_in,
                              void* d_out, int out_size) {
    const float* src = (const float*)d_in[0];
    const float* tgt = (const float*)d_in[1];
    float* out = (float*)d_out;

    dim3 grid(16, 16, 32), block(32, 8);
    k_pass1<<<grid, block>>>(src, tgt);
    k_pass2<<<P2_BLOCKS, 256>>>(src, tgt, out);
}

// round 7
// speedup vs baseline: 1.5849x; 1.5849x over previous
#include <cuda_runtime.h>

#define BB 16
#define HH 512
#define WW 512
#define PL (HH*WW)            // 262144 elems per channel plane
#define NPIX (BB*PL)          // 4194304 pixels per input set
#define P1_BLOCKS (32*256)    // pass1 blocks
#define P2_BLOCKS 512
#define CAP (1<<22)           // candidate capacity (4M)
#define CAND_T 0.0165f        // conservative: 0.001*mean <= 0.016 since ssd < 16

// Static scratch
__device__ float    g_part1[P1_BLOCKS];
__device__ float    g_part2[P2_BLOCKS];
__device__ unsigned g_cand_idx[CAP];   // bit31 = which (0=src,1=tgt), low = pixel idx
__device__ float    g_cand_val[CAP];
__device__ unsigned g_cand_n;
__device__ unsigned g_done2;

__device__ __forceinline__ int clampi(int v, int lo, int hi) {
    return min(max(v, lo), hi);
}

// diff^2 at clamped center (cy,cx) — SAME op order everywhere (bit-exact).
__device__ __forceinline__ float diff2_at(const float* __restrict__ I0,
                                          const float* __restrict__ I1,
                                          const float* __restrict__ I2,
                                          int cy, int cx) {
    int ym = max(cy - 2, 0), yp = min(cy + 2, HH - 1);
    int xm = max(cx - 2, 0), xp = min(cx + 2, WW - 1);
    float d = I0[cy * WW + xm] + I0[yp * WW + xp]
            + I1[yp * WW + xm] + I2[yp * WW + xm]
            - I0[ym * WW + cx] - I1[cy * WW + xm]
            - I2[ym * WW + cx] - I2[yp * WW + xp];
    return d * d;
}

// ssd at pixel (y,x) of an image — bit-exact replica of pass1's 3-stage order.
__device__ float ssd_at(const float* __restrict__ img, int y, int x) {
    const float* I0 = img;
    const float* I1 = img + PL;
    const float* I2 = img + 2 * PL;
    float acc = 0.f;
    #pragma unroll
    for (int dy = -2; dy <= 2; dy++) {
        int yy = clampi(y + dy, 0, HH - 1);
        float hs = 0.f;
        #pragma unroll
        for (int dx = -2; dx <= 2; dx++) {
            int xx = clampi(x + dx, 0, WW - 1);
            hs += diff2_at(I0, I1, I2, yy, xx);
        }
        acc += hs;
    }
    return acc * (1.0f / 25.0f);
}

// ---------------------------------------------------------------------------
// Pass 1: ssd per pixel (never stored) -> per-block partials + candidate list.
// NO threadfence, NO global reduce here (pass2 reduces partials itself).
// grid (16,16,32), block (32,8).
// ---------------------------------------------------------------------------
__global__ __launch_bounds__(256) void k_pass1(const float* __restrict__ src,
                                               const float* __restrict__ tgt) {
    __shared__ float s_d2[36][40];   // diff^2 with +-2 halo (padded stride)
    __shared__ float s_h[36][33];    // horizontal 5-sums
    __shared__ float s_red[8];

    const int tz    = blockIdx.z;
    const int which = tz >> 4;       // 0 = source, 1 = target
    const int b     = tz & 15;
    const float* img = (which ? tgt : src) + (size_t)b * 4 * PL;
    const float* __restrict__ I0 = img;
    const float* __restrict__ I1 = img + PL;
    const float* __restrict__ I2 = img + 2 * PL;

    const int bx = blockIdx.x, by = blockIdx.y;
    const int tx0 = bx * 32;
    const int ty0 = by * 32;
    const int t   = threadIdx.y * 32 + threadIdx.x;
    const bool interior = (bx >= 1) && (bx <= 14) && (by >= 1) && (by <= 14);

    // ---- Stage A: diff^2 over the 36x36 halo region (direct LDG, L1 reuse) ----
    if (interior) {
        #pragma unroll
        for (int i0 = 0; i0 < 36 * 36; i0 += 256 * 2) {
            #pragma unroll
            for (int u = 0; u < 2; u++) {
                int i = i0 + u * 256 + t;
                if (i < 36 * 36) {
                    int ty = i / 36, tx = i - ty * 36;
                    int base = (ty0 - 2 + ty) * WW + (tx0 - 2 + tx);
                    float d = I0[base - 2] + I0[base + 2 * WW + 2]
                            + I1[base + 2 * WW - 2] + I2[base + 2 * WW - 2]
                            - I0[base - 2 * WW] - I1[base - 2]
                            - I2[base - 2 * WW] - I2[base + 2 * WW + 2];
                    s_d2[ty][tx] = d * d;
                }
            }
        }
    } else {
        for (int i = t; i < 36 * 36; i += 256) {
            int ty = i / 36, tx = i - ty * 36;
            int cy = clampi(ty0 - 2 + ty, 0, HH - 1);
            int cx = clampi(tx0 - 2 + tx, 0, WW - 1);
            s_d2[ty][tx] = diff2_at(I0, I1, I2, cy, cx);
        }
    }
    __syncthreads();

    // ---- Stage B: horizontal 5-sum ----
    if (interior) {
        for (int i = t; i < 36 * 32; i += 256) {
            int r = i >> 5, c = i & 31;
            s_h[r][c] = s_d2[r][c] + s_d2[r][c + 1] + s_d2[r][c + 2]
                      + s_d2[r][c + 3] + s_d2[r][c + 4];
        }
    } else {
        for (int i = t; i < 36 * 32; i += 256) {
            int r = i >> 5, c = i & 31;
            int gx = tx0 + c;
            float s = 0.f;
            #pragma unroll
            for (int dx = -2; dx <= 2; dx++) {
                int sx = clampi(gx + dx, 0, WW - 1) - tx0 + 2;
                s += s_d2[r][sx];
            }
            s_h[r][c] = s;
        }
    }
    __syncthreads();

    // ---- Stage C: vertical 5-sum, accumulate, record candidates ----
    float lsum = 0.f;
    const int c = threadIdx.x;
    #pragma unroll
    for (int k = 0; k < 4; k++) {
        int y  = threadIdx.y + k * 8;
        int gy = ty0 + y;
        float s;
        if (interior) {
            s = s_h[y][c] + s_h[y + 1][c] + s_h[y + 2][c]
              + s_h[y + 3][c] + s_h[y + 4][c];
        } else {
            s = 0.f;
            #pragma unroll
            for (int dy = -2; dy <= 2; dy++) {
                int sy = clampi(gy + dy, 0, HH - 1) - ty0 + 2;
                s += s_h[sy][c];
            }
        }
        s *= (1.0f / 25.0f);
        lsum += s;
        if (s < CAND_T) {
            unsigned slot = atomicAdd(&g_cand_n, 1u);
            if (slot < CAP) {
                g_cand_idx[slot] = ((unsigned)which << 31)
                                 | (unsigned)(b * PL + gy * WW + tx0 + c);
                g_cand_val[slot] = s;
            }
        }
    }

    // block reduction -> per-block partial (plain store; pass2 reads it)
    #pragma unroll
    for (int o = 16; o; o >>= 1) lsum += __shfl_down_sync(0xffffffffu, lsum, o);
    if (threadIdx.x == 0) s_red[threadIdx.y] = lsum;
    __syncthreads();
    if (t < 8) {
        float v = s_red[t];
        #pragma unroll
        for (int o = 4; o; o >>= 1) v += __shfl_down_sync(0xffu, v, o);
        if (t == 0) g_part1[tz * 256 + by * 16 + bx] = v;
    }
}

// ---------------------------------------------------------------------------
// Pass 2: each block redundantly reduces pass1 partials (L2 hits) to get the
// per-input means, then computes the loss from candidates only (unclipped
// pairs contribute exactly 0: exp(-x/(0.25x)) == exp(-4) bit-exactly).
// Last block reduces partials, writes out, resets state for graph replay.
// ---------------------------------------------------------------------------
__global__ __launch_bounds__(256) void k_pass2(const float* __restrict__ src,
                                               const float* __restrict__ tgt,
                                               float* __restrict__ out) {
    // --- per-block reduce of g_part1 (first 4096 = source, next 4096 = target)
    __shared__ float s_bcast[2];
    {
        const float4* p4 = (const float4*)g_part1;
        float accS = 0.f, accT = 0.f;
        for (int i = threadIdx.x; i < 1024; i += 256) {
            float4 a = p4[i];
            accS += (a.x + a.y) + (a.z + a.w);
            float4 bq = p4[i + 1024];
            accT += (bq.x + bq.y) + (bq.z + bq.w);
        }
        #pragma unroll
        for (int o = 16; o; o >>= 1) {
            accS += __shfl_down_sync(0xffffffffu, accS, o);
            accT += __shfl_down_sync(0xffffffffu, accT, o);
        }
        __shared__ float sS[8], sT[8];
        if ((threadIdx.x & 31) == 0) {
            sS[threadIdx.x >> 5] = accS; sT[threadIdx.x >> 5] = accT;
        }
        __syncthreads();
        if (threadIdx.x == 0) {
            float fS = 0.f, fT = 0.f;
            #pragma unroll
            for (int j = 0; j < 8; j++) { fS += sS[j]; fT += sT[j]; }
            s_bcast[0] = fS; s_bcast[1] = fT;
        }
        __syncthreads();
    }
    const float sumS = s_bcast[0], sumT = s_bcast[1];

    const float meanS = sumS * (1.0f / (float)NPIX);
    const float meanT = sumT * (1.0f / (float)NPIX);
    const unsigned cn = g_cand_n;
    const bool full = (meanS < CAND_T) || (meanT < CAND_T) || (cn > CAP);
    const unsigned n = cn > CAP ? CAP : cn;

    const float mv_s = (float)((double)sumS / (4.0 * (double)NPIX));
    const float mv_t = (float)((double)sumT / (4.0 * (double)NPIX));
    const float lo_s = mv_s * 0.001f, hi_s = mv_s * 1000.0f;
    const float lo_t = mv_t * 0.001f, hi_t = mv_t * 1000.0f;

    const int tid = blockIdx.x * 256 + threadIdx.x;
    const int stride = gridDim.x * 256;
    float acc = 0.f;

    if (!full) {
        for (unsigned e = tid; e < n; e += stride) {
            unsigned rec = g_cand_idx[e];
            float val = g_cand_val[e];
            int w = rec >> 31;
            unsigned idx = rec & 0x7fffffffu;
            int b = idx / PL; int rem = idx - b * PL;
            int y = rem / WW; int x = rem - y * WW;
            const float* oimg = (w ? src : tgt) + (size_t)b * 4 * PL;
            float other = ssd_at(oimg, y, x);
            float a, bt;
            if (w == 0) { a = val; bt = other; }
            else {
                a = other; bt = val;
                // skip iff source side is itself a candidate: that entry
                // computed the whole pair (prevents double count).
                if (a < CAND_T) continue;
            }
            float va = fminf(fmaxf(a  * 0.25f, lo_s), hi_s);
            float vb = fminf(fmaxf(bt * 0.25f, lo_t), hi_t);
            float d = __expf(-a / va) - __expf(-bt / vb);
            acc += d * d;
        }
    } else {
        // never-taken safety path: full recompute of both ssd fields
        for (long i = tid; i < (long)NPIX; i += stride) {
            int b = (int)(i / PL); int rem = (int)(i - (long)b * PL);
            int y = rem / WW; int x = rem - y * WW;
            float a  = ssd_at(src + (size_t)b * 4 * PL, y, x);
            float bt = ssd_at(tgt + (size_t)b * 4 * PL, y, x);
            float va = fminf(fmaxf(a  * 0.25f, lo_s), hi_s);
            float vb = fminf(fmaxf(bt * 0.25f, lo_t), hi_t);
            float d = __expf(-a / va) - __expf(-bt / vb);
            acc += d * d;
        }
    }

    __shared__ float s_red[8];
    __shared__ int   s_last;
    #pragma unroll
    for (int o = 16; o; o >>= 1) acc += __shfl_down_sync(0xffffffffu, acc, o);
    if ((threadIdx.x & 31) == 0) s_red[threadIdx.x >> 5] = acc;
    __syncthreads();
    if (threadIdx.x < 8) {
        float v = s_red[threadIdx.x];
        #pragma unroll
        for (int o = 4; o; o >>= 1) v += __shfl_down_sync(0xffu, v, o);
        if (threadIdx.x == 0) g_part2[blockIdx.x] = v;
    }

    if (threadIdx.x == 0) {
        __threadfence();
        unsigned v = atomicAdd(&g_done2, 1u);
        s_last = (v == P2_BLOCKS - 1);
    }
    __syncthreads();
    if (s_last) {
        float a2 = g_part2[threadIdx.x];
        float a3 = g_part2[threadIdx.x + 256];
        float v = a2 + a3;
        #pragma unroll
        for (int o = 16; o; o >>= 1) v += __shfl_down_sync(0xffffffffu, v, o);
        __shared__ float s_f[8];
        if ((threadIdx.x & 31) == 0) s_f[threadIdx.x >> 5] = v;
        __syncthreads();
        if (threadIdx.x == 0) {
            float tot = 0.f;
            #pragma unroll
            for (int j = 0; j < 8; j++) tot += s_f[j];
            out[0] = (float)((double)tot / (3.0 * (double)NPIX));
            g_done2 = 0;
            g_cand_n = 0;   // reset for next graph replay
        }
    }
}

extern "C" void kernel_launch(void* const* d_in, const int* in_sizes, int n_in,
                              void* d_out, int out_size) {
    const float* src = (const float*)d_in[0];
    const float* tgt = (const float*)d_in[1];
    float* out = (float*)d_out;

    dim3 grid(16, 16, 32), block(32, 8);
    k_pass1<<<grid, block>>>(src, tgt);
    k_pass2<<<P2_BLOCKS, 256>>>(src, tgt, out);
}